// round 12
// baseline (speedup 1.0000x reference)
#include <cuda_runtime.h>
#include <cuda_bf16.h>
#include <cstdint>

// Problem constants
#define BB 8
#define TT 2048
#define CC 1024
#define HH 64
#define MM (BB * TT)   // 16384 rows

// Single dynamic-smem symbol shared by all kernels
extern __shared__ char dyn_smem[];

// ---------------------------------------------------------------------------
// Static device scratch (allocation-free)
// ---------------------------------------------------------------------------
__device__ __nv_bfloat16 g_wthi[3][HH * CC];   // W transposed: [n][k]
__device__ __nv_bfloat16 g_wtlo[3][HH * CC];
__device__ __nv_bfloat16 g_qhi[MM * HH];
__device__ __nv_bfloat16 g_qlo[MM * HH];
__device__ __nv_bfloat16 g_khi[MM * HH];
__device__ __nv_bfloat16 g_klo[MM * HH];
__device__ __nv_bfloat16 g_vthi[HH * MM];      // V transposed [dim][m]
__device__ __nv_bfloat16 g_vtlo[HH * MM];
__device__ float g_os[2][MM * HH];
__device__ float g_mstat[2][MM];
__device__ float g_lstat[2][MM];

// ---------------------------------------------------------------------------
// PTX helpers (all baseline PTX — legal on compute_103)
// ---------------------------------------------------------------------------
__device__ __forceinline__ uint32_t smem_u32(const void* p) {
    uint32_t a;
    asm("{ .reg .u64 t; cvta.to.shared.u64 t, %1; cvt.u32.u64 %0, t; }"
        : "=r"(a) : "l"(p));
    return a;
}

__device__ __forceinline__ void cp16(uint32_t s, const void* g) {
    asm volatile("cp.async.cg.shared.global [%0], [%1], 16;" :: "r"(s), "l"(g));
}
#define CP_COMMIT() asm volatile("cp.async.commit_group;")

// D(16x8,f32) += A(16x16,bf16 row) * B(16x8,bf16 col)
__device__ __forceinline__ void mma_bf16(float* c, const uint32_t* a, const uint32_t* b)
{
    asm volatile(
        "mma.sync.aligned.m16n8k16.row.col.f32.bf16.bf16.f32 "
        "{%0,%1,%2,%3}, {%4,%5,%6,%7}, {%8,%9}, {%0,%1,%2,%3};"
        : "+f"(c[0]), "+f"(c[1]), "+f"(c[2]), "+f"(c[3])
        : "r"(a[0]), "r"(a[1]), "r"(a[2]), "r"(a[3]), "r"(b[0]), "r"(b[1]));
}

__device__ __forceinline__ uint32_t packbf(float a, float b)
{
    __nv_bfloat162 t;
    t.x = __float2bfloat16(a);
    t.y = __float2bfloat16(b);
    return *(uint32_t*)&t;
}

// ---------------------------------------------------------------------------
// Convert + transpose W -> [n][k] bf16 hi/lo. grid = 3*CC*HH/256 = 768.
// ---------------------------------------------------------------------------
__global__ __launch_bounds__(256) void convert_w_kernel(
    const float* __restrict__ Wq, const float* __restrict__ Wk, const float* __restrict__ Wv)
{
    int idx = blockIdx.x * 256 + threadIdx.x;
    int mat = idx / (CC * HH);
    int rem = idx - mat * (CC * HH);
    int k = rem >> 6;
    int n = rem & 63;
    const float* W = (mat == 0) ? Wq : (mat == 1) ? Wk : Wv;
    float f = W[rem];
    __nv_bfloat16 h = __float2bfloat16(f);
    __nv_bfloat16 l = __float2bfloat16(f - __bfloat162float(h));
    g_wthi[mat][n * CC + k] = h;
    g_wtlo[mat][n * CC + k] = l;
}

// ---------------------------------------------------------------------------
// Kernel: QKV projection, fused fp32->bf16 hi/lo convert + register-prefetch
// pipeline + mma.sync 3-pass.
// NOW: BM=64, block=256, warp grid 4x2 (m16 x n32 per warp) -> ~half the
// per-thread registers -> 2 CTAs/SM. grid = (MM/64, 3).
// ---------------------------------------------------------------------------
#define ASTR 72   // smem row stride in halves (64 data + 8 pad)

#define PROJ_SMEM_BYTES ((2 * 64 * ASTR + 2 * 64 * ASTR) * 2)   // 36864 B

__global__ __launch_bounds__(256) void proj_mma_kernel(const float* __restrict__ x)
{
    uint16_t* sm16 = (uint16_t*)dyn_smem;
    uint16_t* Ahi = sm16;
    uint16_t* Alo = Ahi + 64 * ASTR;
    uint16_t* Bhi = Alo + 64 * ASTR;
    uint16_t* Blo = Bhi + 64 * ASTR;

    const int tid = threadIdx.x;
    const int wid = tid >> 5;
    const int lid = tid & 31;
    const int g   = lid >> 2;
    const int t   = lid & 3;

    const int mw = (wid >> 1) * 16;   // warp m offset (4 bands of 16)
    const int nw = (wid & 1) * 32;    // warp n offset (2 halves of 32)

    const int mat = blockIdx.y;
    const int m0  = blockIdx.x * 64;

    const __nv_bfloat16* wth = g_wthi[mat];
    const __nv_bfloat16* wtl = g_wtlo[mat];

    float c[4][4] = {};   // [nb][reg]

    float4 ax[4];
    uint4  brh[2], brl[2];

    // ---- prologue: load chunk 0
    #pragma unroll
    for (int i = 0; i < 4; i++) {
        int idx = tid + i * 256;
        int r = idx >> 4, c4 = idx & 15;
        ax[i] = *(const float4*)&x[(size_t)(m0 + r) * CC + c4 * 4];
    }
    #pragma unroll
    for (int i = 0; i < 2; i++) {
        int idx = tid + i * 256;
        int r = idx >> 3, c8 = idx & 7;
        brh[i] = *(const uint4*)&wth[(size_t)r * CC + c8 * 8];
        brl[i] = *(const uint4*)&wtl[(size_t)r * CC + c8 * 8];
    }

    for (int ch = 0; ch < 16; ch++) {
        // ---- store prefetched regs -> smem (convert A fp32 to hi/lo)
        #pragma unroll
        for (int i = 0; i < 4; i++) {
            int idx = tid + i * 256;
            int r = idx >> 4, c4 = idx & 15;
            float4 v = ax[i];
            uint32_t h0 = packbf(v.x, v.y);
            uint32_t h1 = packbf(v.z, v.w);
            __nv_bfloat162 hb0 = *(__nv_bfloat162*)&h0;
            __nv_bfloat162 hb1 = *(__nv_bfloat162*)&h1;
            uint32_t l0 = packbf(v.x - __bfloat162float(hb0.x), v.y - __bfloat162float(hb0.y));
            uint32_t l1 = packbf(v.z - __bfloat162float(hb1.x), v.w - __bfloat162float(hb1.y));
            *(uint2*)(Ahi + r * ASTR + c4 * 4) = make_uint2(h0, h1);
            *(uint2*)(Alo + r * ASTR + c4 * 4) = make_uint2(l0, l1);
        }
        #pragma unroll
        for (int i = 0; i < 2; i++) {
            int idx = tid + i * 256;
            int r = idx >> 3, c8 = idx & 7;
            *(uint4*)(Bhi + r * ASTR + c8 * 8) = brh[i];
            *(uint4*)(Blo + r * ASTR + c8 * 8) = brl[i];
        }
        __syncthreads();

        // ---- issue loads for next chunk (latency hidden under MMAs)
        if (ch < 15) {
            const int k0n = (ch + 1) * 64;
            #pragma unroll
            for (int i = 0; i < 4; i++) {
                int idx = tid + i * 256;
                int r = idx >> 4, c4 = idx & 15;
                ax[i] = *(const float4*)&x[(size_t)(m0 + r) * CC + k0n + c4 * 4];
            }
            #pragma unroll
            for (int i = 0; i < 2; i++) {
                int idx = tid + i * 256;
                int r = idx >> 3, c8 = idx & 7;
                brh[i] = *(const uint4*)&wth[(size_t)r * CC + k0n + c8 * 8];
                brl[i] = *(const uint4*)&wtl[(size_t)r * CC + k0n + c8 * 8];
            }
        }

        // ---- MMAs on current smem tiles (scalar fragment loads)
        #pragma unroll
        for (int ks = 0; ks < 4; ks++) {
            const int kk = ks * 16;
            uint32_t ah[4], al[4], bh[4][2], bl[4][2];
            {
                const uint16_t* A0h = Ahi + mw * ASTR + kk;
                const uint16_t* A0l = Alo + mw * ASTR + kk;
                ah[0] = *(const uint32_t*)(A0h + g * ASTR + 2 * t);
                ah[1] = *(const uint32_t*)(A0h + (g + 8) * ASTR + 2 * t);
                ah[2] = *(const uint32_t*)(A0h + g * ASTR + 2 * t + 8);
                ah[3] = *(const uint32_t*)(A0h + (g + 8) * ASTR + 2 * t + 8);
                al[0] = *(const uint32_t*)(A0l + g * ASTR + 2 * t);
                al[1] = *(const uint32_t*)(A0l + (g + 8) * ASTR + 2 * t);
                al[2] = *(const uint32_t*)(A0l + g * ASTR + 2 * t + 8);
                al[3] = *(const uint32_t*)(A0l + (g + 8) * ASTR + 2 * t + 8);
            }
            #pragma unroll
            for (int nb = 0; nb < 4; nb++) {
                const uint16_t* B0h = Bhi + (nw + nb * 8 + g) * ASTR + kk;
                const uint16_t* B0l = Blo + (nw + nb * 8 + g) * ASTR + kk;
                bh[nb][0] = *(const uint32_t*)(B0h + 2 * t);
                bh[nb][1] = *(const uint32_t*)(B0h + 2 * t + 8);
                bl[nb][0] = *(const uint32_t*)(B0l + 2 * t);
                bl[nb][1] = *(const uint32_t*)(B0l + 2 * t + 8);
            }
            #pragma unroll
            for (int nb = 0; nb < 4; nb++) {
                mma_bf16(c[nb], ah, bh[nb]);
                mma_bf16(c[nb], ah, bl[nb]);
                mma_bf16(c[nb], al, bh[nb]);
            }
        }
        __syncthreads();
    }

    // Epilogue -> bf16 hi/lo
    {
        const int r0 = m0 + mw + g;
        const int r1 = r0 + 8;
        #pragma unroll
        for (int nb = 0; nb < 4; nb++) {
            const int col = nw + nb * 8 + 2 * t;
            float v00 = c[nb][0], v01 = c[nb][1];
            float v10 = c[nb][2], v11 = c[nb][3];
            uint32_t h0 = packbf(v00, v01);
            uint32_t h1 = packbf(v10, v11);
            __nv_bfloat162 h0b = *(__nv_bfloat162*)&h0;
            __nv_bfloat162 h1b = *(__nv_bfloat162*)&h1;
            uint32_t l0 = packbf(v00 - __bfloat162float(h0b.x), v01 - __bfloat162float(h0b.y));
            uint32_t l1 = packbf(v10 - __bfloat162float(h1b.x), v11 - __bfloat162float(h1b.y));
            if (mat == 0) {
                *(uint32_t*)&g_qhi[(size_t)r0 * HH + col] = h0;
                *(uint32_t*)&g_qlo[(size_t)r0 * HH + col] = l0;
                *(uint32_t*)&g_qhi[(size_t)r1 * HH + col] = h1;
                *(uint32_t*)&g_qlo[(size_t)r1 * HH + col] = l1;
            } else if (mat == 1) {
                *(uint32_t*)&g_khi[(size_t)r0 * HH + col] = h0;
                *(uint32_t*)&g_klo[(size_t)r0 * HH + col] = l0;
                *(uint32_t*)&g_khi[(size_t)r1 * HH + col] = h1;
                *(uint32_t*)&g_klo[(size_t)r1 * HH + col] = l1;
            } else {
                __nv_bfloat162 l0b = *(__nv_bfloat162*)&l0;
                __nv_bfloat162 l1b = *(__nv_bfloat162*)&l1;
                g_vthi[(size_t)col * MM + r0]       = h0b.x;
                g_vthi[(size_t)(col + 1) * MM + r0] = h0b.y;
                g_vthi[(size_t)col * MM + r1]       = h1b.x;
                g_vthi[(size_t)(col + 1) * MM + r1] = h1b.y;
                g_vtlo[(size_t)col * MM + r0]       = l0b.x;
                g_vtlo[(size_t)(col + 1) * MM + r0] = l0b.y;
                g_vtlo[(size_t)col * MM + r1]       = l1b.x;
                g_vtlo[(size_t)(col + 1) * MM + r1] = l1b.y;
            }
        }
    }
}

// ---------------------------------------------------------------------------
// Kernel: causal flash attention, mma.sync bf16 3-pass, split-K=2,
// cp.async double-buffered K/V pipeline, scalar fragment loads.
// 128 threads / 4 warps / 64 queries per CTA -> 3 CTAs/SM by smem.
// grid = (32, 8, 2), block = 128.   (round-11 winner, unchanged)
// ---------------------------------------------------------------------------
#define TILE_H (64 * ASTR)                      // halves per array
#define ATTN_SMEM_BYTES (2 * 4 * TILE_H * 2)    // 73728 B

__global__ __launch_bounds__(128) void attn_kernel()
{
    uint16_t* sm16 = (uint16_t*)dyn_smem;
    const uint32_t sb = smem_u32(sm16);

    const int qt    = 31 - (int)blockIdx.x;        // heavy-first
    const int b     = blockIdx.y;
    const int split = blockIdx.z;
    const int tid = threadIdx.x;
    const int w   = tid >> 5;   // 0..3
    const int lid = tid & 31;
    const int g   = lid >> 2;
    const int t   = lid & 3;

    const int q0      = qt * 64;
    const int rowbase = b * TT + q0;

    const int nk    = qt + 1;                      // 64-key tiles in causal range
    const int half  = (nk + 1) >> 1;
    const int klo_t = split ? half : 0;
    const int khi_t = split ? nk : half;

    float* Oout = g_os[split];

    if (klo_t >= khi_t) {
        // empty split (qt==0, split==1): O=0, m=-inf, l=0
        for (int i = tid; i < 64 * 16; i += 128) {
            int row = i >> 4, c4 = i & 15;
            *(float4*)&Oout[(size_t)(rowbase + row) * HH + c4 * 4] =
                make_float4(0.f, 0.f, 0.f, 0.f);
        }
        if (tid < 64) {
            g_mstat[split][rowbase + tid] = -1e30f;
            g_lstat[split][rowbase + tid] = 0.0f;
        }
        return;
    }

    // ---- stage Q (64 rows) via stage-0 buffers, then fragments to registers
    uint16_t* Sq_hi = sm16;
    uint16_t* Sq_lo = sm16 + TILE_H;
    #pragma unroll
    for (int i = 0; i < 4; i++) {
        int idx = tid + i * 128;
        int r = idx >> 3, c8 = idx & 7;
        size_t gaddr = (size_t)(rowbase + r) * HH + c8 * 8;
        *(uint4*)(Sq_hi + r * ASTR + c8 * 8) = *(const uint4*)&g_qhi[gaddr];
        *(uint4*)(Sq_lo + r * ASTR + c8 * 8) = *(const uint4*)&g_qlo[gaddr];
    }
    __syncthreads();
    uint32_t qh[4][4], ql[4][4];
    {
        const int lr = w * 16;
        #pragma unroll
        for (int ks = 0; ks < 4; ks++) {
            const uint16_t* Qh0 = Sq_hi + (lr + g) * ASTR + ks * 16;
            const uint16_t* Ql0 = Sq_lo + (lr + g) * ASTR + ks * 16;
            qh[ks][0] = *(const uint32_t*)(Qh0 + 2 * t);
            qh[ks][1] = *(const uint32_t*)(Qh0 + 8 * ASTR + 2 * t);
            qh[ks][2] = *(const uint32_t*)(Qh0 + 2 * t + 8);
            qh[ks][3] = *(const uint32_t*)(Qh0 + 8 * ASTR + 2 * t + 8);
            ql[ks][0] = *(const uint32_t*)(Ql0 + 2 * t);
            ql[ks][1] = *(const uint32_t*)(Ql0 + 8 * ASTR + 2 * t);
            ql[ks][2] = *(const uint32_t*)(Ql0 + 2 * t + 8);
            ql[ks][3] = *(const uint32_t*)(Ql0 + 8 * ASTR + 2 * t + 8);
        }
    }
    __syncthreads();

    const int qrow0 = q0 + w * 16 + g;
    const int qrow1 = qrow0 + 8;

    float o[8][4] = {};
    float m0r = -1e30f, m1r = -1e30f;
    float l0r = 0.0f,   l1r = 0.0f;

    // ---- cp.async tile preloader: K[key][dim] hi/lo + Vt[dim][key] hi/lo
    auto preload = [&](int kt, int st) {
        const int kb = kt * 64;
        const uint32_t s0 = sb + (uint32_t)st * 4 * TILE_H * 2;
        #pragma unroll
        for (int i = 0; i < 4; i++) {
            int idx = tid + i * 128;
            int r = idx >> 3, c8 = idx & 7;
            uint32_t soff = (uint32_t)(r * ASTR + c8 * 8) * 2;
            size_t ka = (size_t)(b * TT + kb + r) * HH + c8 * 8;
            size_t va = (size_t)r * MM + b * TT + kb + c8 * 8;
            cp16(s0 + soff,                  &g_khi[ka]);
            cp16(s0 + TILE_H * 2 + soff,     &g_klo[ka]);
            cp16(s0 + 2 * TILE_H * 2 + soff, &g_vthi[va]);
            cp16(s0 + 3 * TILE_H * 2 + soff, &g_vtlo[va]);
        }
        CP_COMMIT();
    };

    preload(klo_t, 0);

    for (int kt = klo_t; kt < khi_t; kt++) {
        const int kb = kt * 64;
        const int st = (kt - klo_t) & 1;
        const bool more = (kt + 1 < khi_t);
        if (more) preload(kt + 1, st ^ 1);
        if (more) asm volatile("cp.async.wait_group 1;");
        else      asm volatile("cp.async.wait_group 0;");
        __syncthreads();

        uint16_t* Khi  = sm16 + st * 4 * TILE_H;
        uint16_t* Klo  = Khi + TILE_H;
        uint16_t* Vthi = Khi + 2 * TILE_H;
        uint16_t* Vtlo = Khi + 3 * TILE_H;

        // ---- S = Q K^T (3-pass hi/lo)
        float s[8][4] = {};
        #pragma unroll
        for (int ks = 0; ks < 4; ks++) {
            #pragma unroll
            for (int nb = 0; nb < 8; nb++) {
                const uint16_t* K0h = Khi + (nb * 8 + g) * ASTR + ks * 16;
                const uint16_t* K0l = Klo + (nb * 8 + g) * ASTR + ks * 16;
                uint32_t kh[2], kl[2];
                kh[0] = *(const uint32_t*)(K0h + 2 * t);
                kh[1] = *(const uint32_t*)(K0h + 2 * t + 8);
                kl[0] = *(const uint32_t*)(K0l + 2 * t);
                kl[1] = *(const uint32_t*)(K0l + 2 * t + 8);
                mma_bf16(s[nb], qh[ks], kh);
                mma_bf16(s[nb], qh[ks], kl);
                mma_bf16(s[nb], ql[ks], kh);
            }
        }

        // ---- scale + causal mask
        const bool maskTile = (kb + 63 > q0);
        #pragma unroll
        for (int nb = 0; nb < 8; nb++) {
            const int key0 = kb + nb * 8 + 2 * t;
            s[nb][0] *= 0.125f; s[nb][1] *= 0.125f;
            s[nb][2] *= 0.125f; s[nb][3] *= 0.125f;
            if (maskTile) {
                if (key0     > qrow0) s[nb][0] = -1e38f;
                if (key0 + 1 > qrow0) s[nb][1] = -1e38f;
                if (key0     > qrow1) s[nb][2] = -1e38f;
                if (key0 + 1 > qrow1) s[nb][3] = -1e38f;
            }
        }

        // ---- online softmax (rows g and g+8), reduce over 4-lane t-group
        float mx0 = -1e38f, mx1 = -1e38f;
        #pragma unroll
        for (int nb = 0; nb < 8; nb++) {
            mx0 = fmaxf(mx0, fmaxf(s[nb][0], s[nb][1]));
            mx1 = fmaxf(mx1, fmaxf(s[nb][2], s[nb][3]));
        }
        mx0 = fmaxf(mx0, __shfl_xor_sync(0xffffffffu, mx0, 1));
        mx0 = fmaxf(mx0, __shfl_xor_sync(0xffffffffu, mx0, 2));
        mx1 = fmaxf(mx1, __shfl_xor_sync(0xffffffffu, mx1, 1));
        mx1 = fmaxf(mx1, __shfl_xor_sync(0xffffffffu, mx1, 2));

        const float nm0 = fmaxf(m0r, mx0);
        const float nm1 = fmaxf(m1r, mx1);
        const float al0 = __expf(m0r - nm0);
        const float al1 = __expf(m1r - nm1);
        float sum0 = 0.0f, sum1 = 0.0f;
        #pragma unroll
        for (int nb = 0; nb < 8; nb++) {
            s[nb][0] = __expf(s[nb][0] - nm0);
            s[nb][1] = __expf(s[nb][1] - nm0);
            s[nb][2] = __expf(s[nb][2] - nm1);
            s[nb][3] = __expf(s[nb][3] - nm1);
            sum0 += s[nb][0] + s[nb][1];
            sum1 += s[nb][2] + s[nb][3];
        }
        sum0 += __shfl_xor_sync(0xffffffffu, sum0, 1);
        sum0 += __shfl_xor_sync(0xffffffffu, sum0, 2);
        sum1 += __shfl_xor_sync(0xffffffffu, sum1, 1);
        sum1 += __shfl_xor_sync(0xffffffffu, sum1, 2);
        l0r = l0r * al0 + sum0;  m0r = nm0;
        l1r = l1r * al1 + sum1;  m1r = nm1;
        #pragma unroll
        for (int nb = 0; nb < 8; nb++) {
            o[nb][0] *= al0; o[nb][1] *= al0;
            o[nb][2] *= al1; o[nb][3] *= al1;
        }

        // ---- O += P V (P from registers, 3-pass hi/lo)
        #pragma unroll
        for (int ks = 0; ks < 4; ks++) {
            float p00 = s[2 * ks][0],     p01 = s[2 * ks][1];
            float p02 = s[2 * ks][2],     p03 = s[2 * ks][3];
            float p10 = s[2 * ks + 1][0], p11 = s[2 * ks + 1][1];
            float p12 = s[2 * ks + 1][2], p13 = s[2 * ks + 1][3];
            uint32_t aPh[4], aPl[4];
            aPh[0] = packbf(p00, p01);
            aPh[1] = packbf(p02, p03);
            aPh[2] = packbf(p10, p11);
            aPh[3] = packbf(p12, p13);
            __nv_bfloat162 b0 = *(__nv_bfloat162*)&aPh[0];
            __nv_bfloat162 b1 = *(__nv_bfloat162*)&aPh[1];
            __nv_bfloat162 b2 = *(__nv_bfloat162*)&aPh[2];
            __nv_bfloat162 b3 = *(__nv_bfloat162*)&aPh[3];
            aPl[0] = packbf(p00 - __bfloat162float(b0.x), p01 - __bfloat162float(b0.y));
            aPl[1] = packbf(p02 - __bfloat162float(b1.x), p03 - __bfloat162float(b1.y));
            aPl[2] = packbf(p10 - __bfloat162float(b2.x), p11 - __bfloat162float(b2.y));
            aPl[3] = packbf(p12 - __bfloat162float(b3.x), p13 - __bfloat162float(b3.y));
            #pragma unroll
            for (int nb = 0; nb < 8; nb++) {
                const uint16_t* V0h = Vthi + (nb * 8 + g) * ASTR + ks * 16;
                const uint16_t* V0l = Vtlo + (nb * 8 + g) * ASTR + ks * 16;
                uint32_t vh[2], vl[2];
                vh[0] = *(const uint32_t*)(V0h + 2 * t);
                vh[1] = *(const uint32_t*)(V0h + 2 * t + 8);
                vl[0] = *(const uint32_t*)(V0l + 2 * t);
                vl[1] = *(const uint32_t*)(V0l + 2 * t + 8);
                mma_bf16(o[nb], aPh, vh);
                mma_bf16(o[nb], aPh, vl);
                mma_bf16(o[nb], aPl, vh);
            }
        }
        __syncthreads();   // all warps done with stage st before it is refilled
    }

    // ---- write unnormalized O + stats
    const size_t ob0 = (size_t)(rowbase + w * 16 + g) * HH;
    const size_t ob1 = (size_t)(rowbase + w * 16 + g + 8) * HH;
    #pragma unroll
    for (int nb = 0; nb < 8; nb++) {
        const int col = nb * 8 + 2 * t;
        *(float2*)&Oout[ob0 + col] = make_float2(o[nb][0], o[nb][1]);
        *(float2*)&Oout[ob1 + col] = make_float2(o[nb][2], o[nb][3]);
    }
    if (t == 0) {
        g_mstat[split][rowbase + w * 16 + g]     = m0r;
        g_lstat[split][rowbase + w * 16 + g]     = l0r;
        g_mstat[split][rowbase + w * 16 + g + 8] = m1r;
        g_lstat[split][rowbase + w * 16 + g + 8] = l1r;
    }
}

// ---------------------------------------------------------------------------
// Kernel: merge the two splits.  grid = MM*HH/4/256 = 1024, block 256.
// ---------------------------------------------------------------------------
__global__ __launch_bounds__(256) void merge_kernel(float* __restrict__ out)
{
    int gid = blockIdx.x * 256 + threadIdx.x;
    int row = gid >> 4;
    float m0 = g_mstat[0][row], m1 = g_mstat[1][row];
    float l0 = g_lstat[0][row], l1 = g_lstat[1][row];
    float M  = fmaxf(m0, m1);
    float w0 = __expf(m0 - M);
    float w1 = __expf(m1 - M);
    float inv = 1.0f / (w0 * l0 + w1 * l1);
    float4 a = ((const float4*)g_os[0])[gid];
    float4 b = ((const float4*)g_os[1])[gid];
    float4 r;
    r.x = (w0 * a.x + w1 * b.x) * inv;
    r.y = (w0 * a.y + w1 * b.y) * inv;
    r.z = (w0 * a.z + w1 * b.z) * inv;
    r.w = (w0 * a.w + w1 * b.w) * inv;
    ((float4*)out)[gid] = r;
}

// ---------------------------------------------------------------------------
extern "C" void kernel_launch(void* const* d_in, const int* in_sizes, int n_in,
                              void* d_out, int out_size)
{
    const float* x  = (const float*)d_in[0];
    const float* Wq = (const float*)d_in[1];
    const float* Wk = (const float*)d_in[2];
    const float* Wv = (const float*)d_in[3];
    float* out = (float*)d_out;
    (void)in_sizes; (void)n_in; (void)out_size;

    cudaFuncSetAttribute(proj_mma_kernel, cudaFuncAttributeMaxDynamicSharedMemorySize,
                         PROJ_SMEM_BYTES);
    cudaFuncSetAttribute(attn_kernel, cudaFuncAttributeMaxDynamicSharedMemorySize,
                         ATTN_SMEM_BYTES);

    convert_w_kernel<<<3 * CC * HH / 256, 256>>>(Wq, Wk, Wv);

    dim3 ggrid(MM / 64, 3);
    proj_mma_kernel<<<ggrid, 256, PROJ_SMEM_BYTES>>>(x);

    dim3 agrid(32, BB, 2);
    attn_kernel<<<agrid, 128, ATTN_SMEM_BYTES>>>();

    merge_kernel<<<MM * HH / 4 / 256, 256>>>(out);
}

// round 14
// speedup vs baseline: 1.1115x; 1.1115x over previous
#include <cuda_runtime.h>
#include <cuda_bf16.h>
#include <cstdint>

// Problem constants
#define BB 8
#define TT 2048
#define CC 1024
#define HH 64
#define MM (BB * TT)   // 16384 rows
#define NSPLIT 4

// Single dynamic-smem symbol shared by all kernels
extern __shared__ char dyn_smem[];

// ---------------------------------------------------------------------------
// Static device scratch (allocation-free)
// ---------------------------------------------------------------------------
__device__ __nv_bfloat16 g_wthi[3][HH * CC];   // W transposed: [n][k]
__device__ __nv_bfloat16 g_wtlo[3][HH * CC];
__device__ __nv_bfloat16 g_qhi[MM * HH];
__device__ __nv_bfloat16 g_qlo[MM * HH];
__device__ __nv_bfloat16 g_khi[MM * HH];
__device__ __nv_bfloat16 g_klo[MM * HH];
__device__ __nv_bfloat16 g_vthi[HH * MM];      // V transposed [dim][m]
__device__ __nv_bfloat16 g_vtlo[HH * MM];
__device__ float g_os[NSPLIT][MM * HH];
__device__ float g_mstat[NSPLIT][MM];
__device__ float g_lstat[NSPLIT][MM];

// ---------------------------------------------------------------------------
// PTX helpers (all baseline PTX — legal on compute_103)
// ---------------------------------------------------------------------------
__device__ __forceinline__ uint32_t smem_u32(const void* p) {
    uint32_t a;
    asm("{ .reg .u64 t; cvta.to.shared.u64 t, %1; cvt.u32.u64 %0, t; }"
        : "=r"(a) : "l"(p));
    return a;
}

__device__ __forceinline__ void cp16(uint32_t s, const void* g) {
    asm volatile("cp.async.cg.shared.global [%0], [%1], 16;" :: "r"(s), "l"(g));
}
#define CP_COMMIT() asm volatile("cp.async.commit_group;")

// D(16x8,f32) += A(16x16,bf16 row) * B(16x8,bf16 col)
__device__ __forceinline__ void mma_bf16(float* c, const uint32_t* a, const uint32_t* b)
{
    asm volatile(
        "mma.sync.aligned.m16n8k16.row.col.f32.bf16.bf16.f32 "
        "{%0,%1,%2,%3}, {%4,%5,%6,%7}, {%8,%9}, {%0,%1,%2,%3};"
        : "+f"(c[0]), "+f"(c[1]), "+f"(c[2]), "+f"(c[3])
        : "r"(a[0]), "r"(a[1]), "r"(a[2]), "r"(a[3]), "r"(b[0]), "r"(b[1]));
}

__device__ __forceinline__ uint32_t packbf(float a, float b)
{
    __nv_bfloat162 t;
    t.x = __float2bfloat16(a);
    t.y = __float2bfloat16(b);
    return *(uint32_t*)&t;
}

// ---------------------------------------------------------------------------
// Convert + transpose W -> [n][k] bf16 hi/lo. grid = 3*CC*HH/256 = 768.
// ---------------------------------------------------------------------------
__global__ __launch_bounds__(256) void convert_w_kernel(
    const float* __restrict__ Wq, const float* __restrict__ Wk, const float* __restrict__ Wv)
{
    int idx = blockIdx.x * 256 + threadIdx.x;
    int mat = idx / (CC * HH);
    int rem = idx - mat * (CC * HH);
    int k = rem >> 6;
    int n = rem & 63;
    const float* W = (mat == 0) ? Wq : (mat == 1) ? Wk : Wv;
    float f = W[rem];
    __nv_bfloat16 h = __float2bfloat16(f);
    __nv_bfloat16 l = __float2bfloat16(f - __bfloat162float(h));
    g_wthi[mat][n * CC + k] = h;
    g_wtlo[mat][n * CC + k] = l;
}

// ---------------------------------------------------------------------------
// Kernel: QKV projection (round-11 form: BM=128, block=256, reg-prefetch).
// grid = (MM/128, 3), block = 256.
// ---------------------------------------------------------------------------
#define ASTR 72   // smem row stride in halves (64 data + 8 pad)

#define PROJ_SMEM_BYTES ((2 * 128 * ASTR + 2 * 64 * ASTR) * 2)   // 55296 B

__global__ __launch_bounds__(256) void proj_mma_kernel(const float* __restrict__ x)
{
    uint16_t* sm16 = (uint16_t*)dyn_smem;
    uint16_t* Ahi = sm16;
    uint16_t* Alo = Ahi + 128 * ASTR;
    uint16_t* Bhi = Alo + 128 * ASTR;
    uint16_t* Blo = Bhi + 64 * ASTR;

    const int tid = threadIdx.x;
    const int wid = tid >> 5;
    const int lid = tid & 31;
    const int g   = lid >> 2;
    const int t   = lid & 3;

    const int mw = (wid >> 1) * 32;
    const int nw = (wid & 1) * 32;

    const int mat = blockIdx.y;
    const int m0  = blockIdx.x * 128;

    const __nv_bfloat16* wth = g_wthi[mat];
    const __nv_bfloat16* wtl = g_wtlo[mat];

    float c[2][4][4] = {};

    float4 ax[8];
    uint4  brh[2], brl[2];

    // ---- prologue: load chunk 0
    #pragma unroll
    for (int i = 0; i < 8; i++) {
        int idx = tid + i * 256;
        int r = idx >> 4, c4 = idx & 15;
        ax[i] = *(const float4*)&x[(size_t)(m0 + r) * CC + c4 * 4];
    }
    #pragma unroll
    for (int i = 0; i < 2; i++) {
        int idx = tid + i * 256;
        int r = idx >> 3, c8 = idx & 7;
        brh[i] = *(const uint4*)&wth[(size_t)r * CC + c8 * 8];
        brl[i] = *(const uint4*)&wtl[(size_t)r * CC + c8 * 8];
    }

    for (int ch = 0; ch < 16; ch++) {
        // ---- store prefetched regs -> smem (convert A fp32 to hi/lo)
        #pragma unroll
        for (int i = 0; i < 8; i++) {
            int idx = tid + i * 256;
            int r = idx >> 4, c4 = idx & 15;
            float4 v = ax[i];
            uint32_t h0 = packbf(v.x, v.y);
            uint32_t h1 = packbf(v.z, v.w);
            __nv_bfloat162 hb0 = *(__nv_bfloat162*)&h0;
            __nv_bfloat162 hb1 = *(__nv_bfloat162*)&h1;
            uint32_t l0 = packbf(v.x - __bfloat162float(hb0.x), v.y - __bfloat162float(hb0.y));
            uint32_t l1 = packbf(v.z - __bfloat162float(hb1.x), v.w - __bfloat162float(hb1.y));
            *(uint2*)(Ahi + r * ASTR + c4 * 4) = make_uint2(h0, h1);
            *(uint2*)(Alo + r * ASTR + c4 * 4) = make_uint2(l0, l1);
        }
        #pragma unroll
        for (int i = 0; i < 2; i++) {
            int idx = tid + i * 256;
            int r = idx >> 3, c8 = idx & 7;
            *(uint4*)(Bhi + r * ASTR + c8 * 8) = brh[i];
            *(uint4*)(Blo + r * ASTR + c8 * 8) = brl[i];
        }
        __syncthreads();

        // ---- issue loads for next chunk (latency hidden under MMAs)
        if (ch < 15) {
            const int k0n = (ch + 1) * 64;
            #pragma unroll
            for (int i = 0; i < 8; i++) {
                int idx = tid + i * 256;
                int r = idx >> 4, c4 = idx & 15;
                ax[i] = *(const float4*)&x[(size_t)(m0 + r) * CC + k0n + c4 * 4];
            }
            #pragma unroll
            for (int i = 0; i < 2; i++) {
                int idx = tid + i * 256;
                int r = idx >> 3, c8 = idx & 7;
                brh[i] = *(const uint4*)&wth[(size_t)r * CC + k0n + c8 * 8];
                brl[i] = *(const uint4*)&wtl[(size_t)r * CC + k0n + c8 * 8];
            }
        }

        // ---- MMAs on current smem tiles (scalar fragment loads)
        #pragma unroll
        for (int ks = 0; ks < 4; ks++) {
            const int kk = ks * 16;
            uint32_t ah[2][4], al[2][4], bh[4][2], bl[4][2];
            #pragma unroll
            for (int mb = 0; mb < 2; mb++) {
                const uint16_t* A0h = Ahi + (mw + mb * 16) * ASTR + kk;
                const uint16_t* A0l = Alo + (mw + mb * 16) * ASTR + kk;
                ah[mb][0] = *(const uint32_t*)(A0h + g * ASTR + 2 * t);
                ah[mb][1] = *(const uint32_t*)(A0h + (g + 8) * ASTR + 2 * t);
                ah[mb][2] = *(const uint32_t*)(A0h + g * ASTR + 2 * t + 8);
                ah[mb][3] = *(const uint32_t*)(A0h + (g + 8) * ASTR + 2 * t + 8);
                al[mb][0] = *(const uint32_t*)(A0l + g * ASTR + 2 * t);
                al[mb][1] = *(const uint32_t*)(A0l + (g + 8) * ASTR + 2 * t);
                al[mb][2] = *(const uint32_t*)(A0l + g * ASTR + 2 * t + 8);
                al[mb][3] = *(const uint32_t*)(A0l + (g + 8) * ASTR + 2 * t + 8);
            }
            #pragma unroll
            for (int nb = 0; nb < 4; nb++) {
                const uint16_t* B0h = Bhi + (nw + nb * 8 + g) * ASTR + kk;
                const uint16_t* B0l = Blo + (nw + nb * 8 + g) * ASTR + kk;
                bh[nb][0] = *(const uint32_t*)(B0h + 2 * t);
                bh[nb][1] = *(const uint32_t*)(B0h + 2 * t + 8);
                bl[nb][0] = *(const uint32_t*)(B0l + 2 * t);
                bl[nb][1] = *(const uint32_t*)(B0l + 2 * t + 8);
            }
            #pragma unroll
            for (int mb = 0; mb < 2; mb++)
                #pragma unroll
                for (int nb = 0; nb < 4; nb++) {
                    mma_bf16(c[mb][nb], ah[mb], bh[nb]);
                    mma_bf16(c[mb][nb], ah[mb], bl[nb]);
                    mma_bf16(c[mb][nb], al[mb], bh[nb]);
                }
        }
        __syncthreads();
    }

    // Epilogue -> bf16 hi/lo
    #pragma unroll
    for (int mb = 0; mb < 2; mb++) {
        const int r0 = m0 + mw + mb * 16 + g;
        const int r1 = r0 + 8;
        #pragma unroll
        for (int nb = 0; nb < 4; nb++) {
            const int col = nw + nb * 8 + 2 * t;
            float v00 = c[mb][nb][0], v01 = c[mb][nb][1];
            float v10 = c[mb][nb][2], v11 = c[mb][nb][3];
            uint32_t h0 = packbf(v00, v01);
            uint32_t h1 = packbf(v10, v11);
            __nv_bfloat162 h0b = *(__nv_bfloat162*)&h0;
            __nv_bfloat162 h1b = *(__nv_bfloat162*)&h1;
            uint32_t l0 = packbf(v00 - __bfloat162float(h0b.x), v01 - __bfloat162float(h0b.y));
            uint32_t l1 = packbf(v10 - __bfloat162float(h1b.x), v11 - __bfloat162float(h1b.y));
            if (mat == 0) {
                *(uint32_t*)&g_qhi[(size_t)r0 * HH + col] = h0;
                *(uint32_t*)&g_qlo[(size_t)r0 * HH + col] = l0;
                *(uint32_t*)&g_qhi[(size_t)r1 * HH + col] = h1;
                *(uint32_t*)&g_qlo[(size_t)r1 * HH + col] = l1;
            } else if (mat == 1) {
                *(uint32_t*)&g_khi[(size_t)r0 * HH + col] = h0;
                *(uint32_t*)&g_klo[(size_t)r0 * HH + col] = l0;
                *(uint32_t*)&g_khi[(size_t)r1 * HH + col] = h1;
                *(uint32_t*)&g_klo[(size_t)r1 * HH + col] = l1;
            } else {
                __nv_bfloat162 l0b = *(__nv_bfloat162*)&l0;
                __nv_bfloat162 l1b = *(__nv_bfloat162*)&l1;
                g_vthi[(size_t)col * MM + r0]       = h0b.x;
                g_vthi[(size_t)(col + 1) * MM + r0] = h0b.y;
                g_vthi[(size_t)col * MM + r1]       = h1b.x;
                g_vthi[(size_t)(col + 1) * MM + r1] = h1b.y;
                g_vtlo[(size_t)col * MM + r0]       = l0b.x;
                g_vtlo[(size_t)(col + 1) * MM + r0] = l0b.y;
                g_vtlo[(size_t)col * MM + r1]       = l1b.x;
                g_vtlo[(size_t)(col + 1) * MM + r1] = l1b.y;
            }
        }
    }
}

// ---------------------------------------------------------------------------
// Kernel: causal flash attention, mma.sync bf16 3-pass, SPLIT-K=4,
// cp.async double-buffered K/V pipeline, scalar fragment loads.
// 128 threads / 4 warps / 64 queries per CTA -> 3 CTAs/SM by smem.
// grid = (32, 8, 4), block = 128.
// ---------------------------------------------------------------------------
#define TILE_H (64 * ASTR)                      // halves per array
#define ATTN_SMEM_BYTES (2 * 4 * TILE_H * 2)    // 73728 B

__global__ __launch_bounds__(128) void attn_kernel()
{
    uint16_t* sm16 = (uint16_t*)dyn_smem;
    const uint32_t sb = smem_u32(sm16);

    const int qt    = 31 - (int)blockIdx.x;        // heavy-first
    const int b     = blockIdx.y;
    const int split = blockIdx.z;
    const int tid = threadIdx.x;
    const int w   = tid >> 5;   // 0..3
    const int lid = tid & 31;
    const int g   = lid >> 2;
    const int t   = lid & 3;

    const int q0      = qt * 64;
    const int rowbase = b * TT + q0;

    const int nk    = qt + 1;                      // 64-key tiles in causal range
    const int klo_t = (nk * split) >> 2;           // balanced 4-way split
    const int khi_t = (nk * (split + 1)) >> 2;

    float* Oout = g_os[split];

    if (klo_t >= khi_t) {
        // empty split: O=0, m=-inf, l=0
        for (int i = tid; i < 64 * 16; i += 128) {
            int row = i >> 4, c4 = i & 15;
            *(float4*)&Oout[(size_t)(rowbase + row) * HH + c4 * 4] =
                make_float4(0.f, 0.f, 0.f, 0.f);
        }
        if (tid < 64) {
            g_mstat[split][rowbase + tid] = -1e30f;
            g_lstat[split][rowbase + tid] = 0.0f;
        }
        return;
    }

    // ---- stage Q (64 rows) via stage-0 buffers, then fragments to registers
    uint16_t* Sq_hi = sm16;
    uint16_t* Sq_lo = sm16 + TILE_H;
    #pragma unroll
    for (int i = 0; i < 4; i++) {
        int idx = tid + i * 128;
        int r = idx >> 3, c8 = idx & 7;
        size_t gaddr = (size_t)(rowbase + r) * HH + c8 * 8;
        *(uint4*)(Sq_hi + r * ASTR + c8 * 8) = *(const uint4*)&g_qhi[gaddr];
        *(uint4*)(Sq_lo + r * ASTR + c8 * 8) = *(const uint4*)&g_qlo[gaddr];
    }
    __syncthreads();
    uint32_t qh[4][4], ql[4][4];
    {
        const int lr = w * 16;
        #pragma unroll
        for (int ks = 0; ks < 4; ks++) {
            const uint16_t* Qh0 = Sq_hi + (lr + g) * ASTR + ks * 16;
            const uint16_t* Ql0 = Sq_lo + (lr + g) * ASTR + ks * 16;
            qh[ks][0] = *(const uint32_t*)(Qh0 + 2 * t);
            qh[ks][1] = *(const uint32_t*)(Qh0 + 8 * ASTR + 2 * t);
            qh[ks][2] = *(const uint32_t*)(Qh0 + 2 * t + 8);
            qh[ks][3] = *(const uint32_t*)(Qh0 + 8 * ASTR + 2 * t + 8);
            ql[ks][0] = *(const uint32_t*)(Ql0 + 2 * t);
            ql[ks][1] = *(const uint32_t*)(Ql0 + 8 * ASTR + 2 * t);
            ql[ks][2] = *(const uint32_t*)(Ql0 + 2 * t + 8);
            ql[ks][3] = *(const uint32_t*)(Ql0 + 8 * ASTR + 2 * t + 8);
        }
    }
    __syncthreads();

    const int qrow0 = q0 + w * 16 + g;
    const int qrow1 = qrow0 + 8;

    float o[8][4] = {};
    float m0r = -1e30f, m1r = -1e30f;
    float l0r = 0.0f,   l1r = 0.0f;

    // ---- cp.async tile preloader: K[key][dim] hi/lo + Vt[dim][key] hi/lo
    auto preload = [&](int kt, int st) {
        const int kb = kt * 64;
        const uint32_t s0 = sb + (uint32_t)st * 4 * TILE_H * 2;
        #pragma unroll
        for (int i = 0; i < 4; i++) {
            int idx = tid + i * 128;
            int r = idx >> 3, c8 = idx & 7;
            uint32_t soff = (uint32_t)(r * ASTR + c8 * 8) * 2;
            size_t ka = (size_t)(b * TT + kb + r) * HH + c8 * 8;
            size_t va = (size_t)r * MM + b * TT + kb + c8 * 8;
            cp16(s0 + soff,                  &g_khi[ka]);
            cp16(s0 + TILE_H * 2 + soff,     &g_klo[ka]);
            cp16(s0 + 2 * TILE_H * 2 + soff, &g_vthi[va]);
            cp16(s0 + 3 * TILE_H * 2 + soff, &g_vtlo[va]);
        }
        CP_COMMIT();
    };

    preload(klo_t, 0);

    for (int kt = klo_t; kt < khi_t; kt++) {
        const int kb = kt * 64;
        const int st = (kt - klo_t) & 1;
        const bool more = (kt + 1 < khi_t);
        if (more) preload(kt + 1, st ^ 1);
        if (more) asm volatile("cp.async.wait_group 1;");
        else      asm volatile("cp.async.wait_group 0;");
        __syncthreads();

        uint16_t* Khi  = sm16 + st * 4 * TILE_H;
        uint16_t* Klo  = Khi + TILE_H;
        uint16_t* Vthi = Khi + 2 * TILE_H;
        uint16_t* Vtlo = Khi + 3 * TILE_H;

        // ---- S = Q K^T (3-pass hi/lo)
        float s[8][4] = {};
        #pragma unroll
        for (int ks = 0; ks < 4; ks++) {
            #pragma unroll
            for (int nb = 0; nb < 8; nb++) {
                const uint16_t* K0h = Khi + (nb * 8 + g) * ASTR + ks * 16;
                const uint16_t* K0l = Klo + (nb * 8 + g) * ASTR + ks * 16;
                uint32_t kh[2], kl[2];
                kh[0] = *(const uint32_t*)(K0h + 2 * t);
                kh[1] = *(const uint32_t*)(K0h + 2 * t + 8);
                kl[0] = *(const uint32_t*)(K0l + 2 * t);
                kl[1] = *(const uint32_t*)(K0l + 2 * t + 8);
                mma_bf16(s[nb], qh[ks], kh);
                mma_bf16(s[nb], qh[ks], kl);
                mma_bf16(s[nb], ql[ks], kh);
            }
        }

        // ---- scale + causal mask
        const bool maskTile = (kb + 63 > q0);
        #pragma unroll
        for (int nb = 0; nb < 8; nb++) {
            const int key0 = kb + nb * 8 + 2 * t;
            s[nb][0] *= 0.125f; s[nb][1] *= 0.125f;
            s[nb][2] *= 0.125f; s[nb][3] *= 0.125f;
            if (maskTile) {
                if (key0     > qrow0) s[nb][0] = -1e38f;
                if (key0 + 1 > qrow0) s[nb][1] = -1e38f;
                if (key0     > qrow1) s[nb][2] = -1e38f;
                if (key0 + 1 > qrow1) s[nb][3] = -1e38f;
            }
        }

        // ---- online softmax (rows g and g+8), reduce over 4-lane t-group
        float mx0 = -1e38f, mx1 = -1e38f;
        #pragma unroll
        for (int nb = 0; nb < 8; nb++) {
            mx0 = fmaxf(mx0, fmaxf(s[nb][0], s[nb][1]));
            mx1 = fmaxf(mx1, fmaxf(s[nb][2], s[nb][3]));
        }
        mx0 = fmaxf(mx0, __shfl_xor_sync(0xffffffffu, mx0, 1));
        mx0 = fmaxf(mx0, __shfl_xor_sync(0xffffffffu, mx0, 2));
        mx1 = fmaxf(mx1, __shfl_xor_sync(0xffffffffu, mx1, 1));
        mx1 = fmaxf(mx1, __shfl_xor_sync(0xffffffffu, mx1, 2));

        const float nm0 = fmaxf(m0r, mx0);
        const float nm1 = fmaxf(m1r, mx1);
        const float al0 = __expf(m0r - nm0);
        const float al1 = __expf(m1r - nm1);
        float sum0 = 0.0f, sum1 = 0.0f;
        #pragma unroll
        for (int nb = 0; nb < 8; nb++) {
            s[nb][0] = __expf(s[nb][0] - nm0);
            s[nb][1] = __expf(s[nb][1] - nm0);
            s[nb][2] = __expf(s[nb][2] - nm1);
            s[nb][3] = __expf(s[nb][3] - nm1);
            sum0 += s[nb][0] + s[nb][1];
            sum1 += s[nb][2] + s[nb][3];
        }
        sum0 += __shfl_xor_sync(0xffffffffu, sum0, 1);
        sum0 += __shfl_xor_sync(0xffffffffu, sum0, 2);
        sum1 += __shfl_xor_sync(0xffffffffu, sum1, 1);
        sum1 += __shfl_xor_sync(0xffffffffu, sum1, 2);
        l0r = l0r * al0 + sum0;  m0r = nm0;
        l1r = l1r * al1 + sum1;  m1r = nm1;
        #pragma unroll
        for (int nb = 0; nb < 8; nb++) {
            o[nb][0] *= al0; o[nb][1] *= al0;
            o[nb][2] *= al1; o[nb][3] *= al1;
        }

        // ---- O += P V (P from registers, 3-pass hi/lo)
        #pragma unroll
        for (int ks = 0; ks < 4; ks++) {
            float p00 = s[2 * ks][0],     p01 = s[2 * ks][1];
            float p02 = s[2 * ks][2],     p03 = s[2 * ks][3];
            float p10 = s[2 * ks + 1][0], p11 = s[2 * ks + 1][1];
            float p12 = s[2 * ks + 1][2], p13 = s[2 * ks + 1][3];
            uint32_t aPh[4], aPl[4];
            aPh[0] = packbf(p00, p01);
            aPh[1] = packbf(p02, p03);
            aPh[2] = packbf(p10, p11);
            aPh[3] = packbf(p12, p13);
            __nv_bfloat162 b0 = *(__nv_bfloat162*)&aPh[0];
            __nv_bfloat162 b1 = *(__nv_bfloat162*)&aPh[1];
            __nv_bfloat162 b2 = *(__nv_bfloat162*)&aPh[2];
            __nv_bfloat162 b3 = *(__nv_bfloat162*)&aPh[3];
            aPl[0] = packbf(p00 - __bfloat162float(b0.x), p01 - __bfloat162float(b0.y));
            aPl[1] = packbf(p02 - __bfloat162float(b1.x), p03 - __bfloat162float(b1.y));
            aPl[2] = packbf(p10 - __bfloat162float(b2.x), p11 - __bfloat162float(b2.y));
            aPl[3] = packbf(p12 - __bfloat162float(b3.x), p13 - __bfloat162float(b3.y));
            #pragma unroll
            for (int nb = 0; nb < 8; nb++) {
                const uint16_t* V0h = Vthi + (nb * 8 + g) * ASTR + ks * 16;
                const uint16_t* V0l = Vtlo + (nb * 8 + g) * ASTR + ks * 16;
                uint32_t vh[2], vl[2];
                vh[0] = *(const uint32_t*)(V0h + 2 * t);
                vh[1] = *(const uint32_t*)(V0h + 2 * t + 8);
                vl[0] = *(const uint32_t*)(V0l + 2 * t);
                vl[1] = *(const uint32_t*)(V0l + 2 * t + 8);
                mma_bf16(o[nb], aPh, vh);
                mma_bf16(o[nb], aPh, vl);
                mma_bf16(o[nb], aPl, vh);
            }
        }
        __syncthreads();   // all warps done with stage st before it is refilled
    }

    // ---- write unnormalized O + stats
    const size_t ob0 = (size_t)(rowbase + w * 16 + g) * HH;
    const size_t ob1 = (size_t)(rowbase + w * 16 + g + 8) * HH;
    #pragma unroll
    for (int nb = 0; nb < 8; nb++) {
        const int col = nb * 8 + 2 * t;
        *(float2*)&Oout[ob0 + col] = make_float2(o[nb][0], o[nb][1]);
        *(float2*)&Oout[ob1 + col] = make_float2(o[nb][2], o[nb][3]);
    }
    if (t == 0) {
        g_mstat[split][rowbase + w * 16 + g]     = m0r;
        g_lstat[split][rowbase + w * 16 + g]     = l0r;
        g_mstat[split][rowbase + w * 16 + g + 8] = m1r;
        g_lstat[split][rowbase + w * 16 + g + 8] = l1r;
    }
}

// ---------------------------------------------------------------------------
// Kernel: merge the four splits.  grid = MM*HH/4/256 = 1024, block 256.
// ---------------------------------------------------------------------------
__global__ __launch_bounds__(256) void merge_kernel(float* __restrict__ out)
{
    int gid = blockIdx.x * 256 + threadIdx.x;     // float4 index
    int row = gid >> 4;
    float m[NSPLIT], l[NSPLIT];
    float M = -1e38f;
    #pragma unroll
    for (int s = 0; s < NSPLIT; s++) {
        m[s] = g_mstat[s][row];
        l[s] = g_lstat[s][row];
        M = fmaxf(M, m[s]);
    }
    float wgt[NSPLIT];
    float denom = 0.0f;
    #pragma unroll
    for (int s = 0; s < NSPLIT; s++) {
        wgt[s] = __expf(m[s] - M);
        denom += wgt[s] * l[s];
    }
    const float inv = 1.0f / denom;
    float4 r = make_float4(0.f, 0.f, 0.f, 0.f);
    #pragma unroll
    for (int s = 0; s < NSPLIT; s++) {
        float4 a = ((const float4*)g_os[s])[gid];
        r.x += wgt[s] * a.x;
        r.y += wgt[s] * a.y;
        r.z += wgt[s] * a.z;
        r.w += wgt[s] * a.w;
    }
    r.x *= inv; r.y *= inv; r.z *= inv; r.w *= inv;
    ((float4*)out)[gid] = r;
}

// ---------------------------------------------------------------------------
extern "C" void kernel_launch(void* const* d_in, const int* in_sizes, int n_in,
                              void* d_out, int out_size)
{
    const float* x  = (const float*)d_in[0];
    const float* Wq = (const float*)d_in[1];
    const float* Wk = (const float*)d_in[2];
    const float* Wv = (const float*)d_in[3];
    float* out = (float*)d_out;
    (void)in_sizes; (void)n_in; (void)out_size;

    cudaFuncSetAttribute(proj_mma_kernel, cudaFuncAttributeMaxDynamicSharedMemorySize,
                         PROJ_SMEM_BYTES);
    cudaFuncSetAttribute(attn_kernel, cudaFuncAttributeMaxDynamicSharedMemorySize,
                         ATTN_SMEM_BYTES);

    convert_w_kernel<<<3 * CC * HH / 256, 256>>>(Wq, Wk, Wv);

    dim3 ggrid(MM / 128, 3);
    proj_mma_kernel<<<ggrid, 256, PROJ_SMEM_BYTES>>>(x);

    dim3 agrid(32, BB, NSPLIT);
    attn_kernel<<<agrid, 128, ATTN_SMEM_BYTES>>>();

    merge_kernel<<<MM * HH / 4 / 256, 256>>>(out);
}